// round 8
// baseline (speedup 1.0000x reference)
#include <cuda_runtime.h>
#include <cuda_bf16.h>
#include <cstdint>

// ---------------------------------------------------------------------------
// Problem constants
// ---------------------------------------------------------------------------
#define Bn  8192
#define Dn  1024
#define Hn  8
#define HDn 128
#define BM  64             // rows per CTA
#define NT  512            // threads per CTA (16 warps: 2 M-groups x 8 N-groups)

// A smem tiles: 64 rows x 136 bf16 (128 data + 8 pad -> 272B rows, bank-safe)
#define A_LDE 136
#define A_TILE_BYTES (BM * A_LDE * 2)          // 17408
#define OFF_AHI 0
#define OFF_ALO A_TILE_BYTES
// B double buffer: per kstep 16KB hi + 16KB lo, x2 buffers
#define OFF_B   (2 * A_TILE_BYTES)             // 34816
#define B_SLICE 16384
#define B_BUF   (2 * B_SLICE)                  // 32768 per buffer
#define SMEM_BYTES (OFF_B + 2 * B_BUF)         // 100352

// ---------------------------------------------------------------------------
// Device scratch: W pre-packed in mma.m16n8k16 B-fragment layout (bf16 hi/lo).
// uint32 index: ((((h*8 + ks)*4 + g)*16 + nt)*32 + lane)*2 + r
//   -> per (h,ks) slice = 4096 uint32 = 16KB contiguous (one cp.async stage)
//   reg r uint32 = pack( W[k, n], W[k+1, n] )
//   k = ks*16 + r*8 + (lane&3)*2,  n = nt*8 + (lane>>2)
// ---------------------------------------------------------------------------
#define WFRAG_TOTAL (Hn * 8 * 4 * 16 * 32 * 2) // 262144 uint32
__device__ uint32_t g_Bhi[WFRAG_TOTAL];
__device__ uint32_t g_Blo[WFRAG_TOTAL];
__device__ int g_any_nonzero;

// ---------------------------------------------------------------------------
// Helpers
// ---------------------------------------------------------------------------
__device__ __forceinline__ uint32_t smem_u32(const void* p) {
    uint32_t a;
    asm("{ .reg .u64 t; cvta.to.shared.u64 t, %1; cvt.u32.u64 %0, t; }"
        : "=r"(a) : "l"(p));
    return a;
}

__device__ __forceinline__ void ldsm4(uint32_t* r, uint32_t addr) {
    asm volatile("ldmatrix.sync.aligned.m8n8.x4.shared.b16 {%0,%1,%2,%3}, [%4];"
                 : "=r"(r[0]), "=r"(r[1]), "=r"(r[2]), "=r"(r[3]) : "r"(addr));
}

__device__ __forceinline__ uint2 lds64(uint32_t addr) {
    uint2 v;
    asm volatile("ld.shared.v2.u32 {%0,%1}, [%2];" : "=r"(v.x), "=r"(v.y) : "r"(addr));
    return v;
}

__device__ __forceinline__ void mma_bf16(float* c, const uint32_t* a, uint32_t b0, uint32_t b1) {
    asm volatile("mma.sync.aligned.m16n8k16.row.col.f32.bf16.bf16.f32 "
                 "{%0,%1,%2,%3}, {%4,%5,%6,%7}, {%8,%9}, {%0,%1,%2,%3};"
                 : "+f"(c[0]), "+f"(c[1]), "+f"(c[2]), "+f"(c[3])
                 : "r"(a[0]), "r"(a[1]), "r"(a[2]), "r"(a[3]), "r"(b0), "r"(b1));
}

__device__ __forceinline__ void cp16s(uint32_t s, const void* g) {
    asm volatile("cp.async.cg.shared.global [%0], [%1], 16;" :: "r"(s), "l"(g));
}

__device__ __forceinline__ uint32_t pack_bf16(float a, float b) {
    return (uint32_t)__bfloat16_as_ushort(__float2bfloat16_rn(a)) |
           ((uint32_t)__bfloat16_as_ushort(__float2bfloat16_rn(b)) << 16);
}

// ---------------------------------------------------------------------------
// all(n == 0) flag
// ---------------------------------------------------------------------------
__global__ void reset_flag_kernel() { g_any_nonzero = 0; }

__global__ void scan_n_kernel(const float4* __restrict__ n4, int count) {
    int any = 0;
    int stride = gridDim.x * blockDim.x;
    for (int v = blockIdx.x * blockDim.x + threadIdx.x; v < count; v += stride) {
        float4 x = n4[v];
        any |= (x.x != 0.0f) | (x.y != 0.0f) | (x.z != 0.0f) | (x.w != 0.0f);
    }
    if (__syncthreads_or(any)) {
        if (threadIdx.x == 0) atomicOr(&g_any_nonzero, 1);
    }
}

// ---------------------------------------------------------------------------
// W -> B-fragment converter (one thread per packed uint32)
// ---------------------------------------------------------------------------
__global__ void convert_w_frag(const float* __restrict__ Wi, const float* __restrict__ Wf,
                               const float* __restrict__ Wz, const float* __restrict__ Wo) {
    int id = blockIdx.x * blockDim.x + threadIdx.x;     // 262144 total
    int r    = id & 1;
    int lane = (id >> 1) & 31;
    int nt   = (id >> 6) & 15;
    int g    = (id >> 10) & 3;
    int ks   = (id >> 12) & 7;
    int h    = id >> 15;
    int k = ks * 16 + r * 8 + (lane & 3) * 2;
    int n = nt * 8 + (lane >> 2);
    const float* W = (g == 0) ? Wi : (g == 1) ? Wf : (g == 2) ? Wz : Wo;
    float x0 = W[h * 16384 + k * 128 + n];
    float x1 = W[h * 16384 + (k + 1) * 128 + n];
    float h0 = __bfloat162float(__float2bfloat16_rn(x0));
    float h1 = __bfloat162float(__float2bfloat16_rn(x1));
    g_Bhi[id] = pack_bf16(x0, x1);
    g_Blo[id] = pack_bf16(x0 - h0, x1 - h1);
}

// ---------------------------------------------------------------------------
// sLSTM pointwise cell (validated: rel_err ~1e-7 in f32 path)
// ---------------------------------------------------------------------------
__device__ __forceinline__ void cell_compute(
    float ipre, float fpre, float zpre, float opre,
    float c, float n, float m, bool allzero,
    float& cn, float& nn, float& mn, float& hn)
{
    float og = __fdividef(1.0f, 1.0f + __expf(-opre));
    float lf = fminf(fpre, 0.0f) - __logf(1.0f + __expf(-fabsf(fpre)));
    float a  = lf + m;
    mn = allzero ? ipre : fmaxf(a, ipre);
    float ip = fminf(__expf(ipre - mn), 1.0f);
    float fp = fminf(__expf(a - mn), 1.0f);
    float e2 = __expf(2.0f * zpre);
    float tz = 1.0f - __fdividef(2.0f, e2 + 1.0f);
    cn = fp * c + ip * tz;
    nn = fp * n + ip;
    hn = og * __fdividef(cn, fmaxf(nn, 1e-6f));
}

// ---------------------------------------------------------------------------
// Main kernel: CTA = 64 rows x 1 head
// Warp w: wm = w&1 -> rows [32*wm, 32*wm+32) as 2 m16-tiles
//         wn = w>>1 -> col-tiles {wn*2, wn*2+1} for ALL 4 gates (8 fnt)
// Fused 3-way bf16 split in one k-loop; B staged in smem via cp.async.
// ---------------------------------------------------------------------------
__global__ void __launch_bounds__(NT) slstm_mma_kernel(
    const float* __restrict__ gi, const float* __restrict__ gf,
    const float* __restrict__ gz, const float* __restrict__ go,
    const float* __restrict__ gc, const float* __restrict__ gn,
    const float* __restrict__ gm, const float* __restrict__ gh,
    const float* __restrict__ bi, const float* __restrict__ bf,
    const float* __restrict__ bz, const float* __restrict__ bo,
    float* __restrict__ out)
{
    extern __shared__ char smem[];
    const uint32_t sb = smem_u32(smem);
    const int tid  = threadIdx.x;
    const int w    = tid >> 5;
    const int lane = tid & 31;
    const int wm   = w & 1;
    const int wn   = w >> 1;
    const int head = blockIdx.y;
    const int row0 = blockIdx.x * BM;

    // ---- prefetch B kstep 0 (hi+lo, 32KB) ----
    {
        const char* srch = (const char*)(g_Bhi + ((size_t)head * 8 + 0) * 4096);
        const char* srcl = (const char*)(g_Blo + ((size_t)head * 8 + 0) * 4096);
        uint32_t dst = sb + OFF_B;
#pragma unroll
        for (int it = 0; it < 2; ++it) {
            int ch = (tid + it * NT) * 16;
            cp16s(dst + ch, srch + ch);
            cp16s(dst + B_SLICE + ch, srcl + ch);
        }
        asm volatile("cp.async.commit_group;");
    }

    // ---- load h tile (64x128 f32), split hi/lo bf16 into smem ----
#pragma unroll
    for (int it = 0; it < (BM * HDn / 4) / NT; ++it) {   // 4 iters
        int v = tid + it * NT;
        int r = v >> 5;
        int kq = (v & 31) * 4;
        float4 x = *(const float4*)&gh[(size_t)(row0 + r) * Dn + head * HDn + kq];
        float h0 = __bfloat162float(__float2bfloat16_rn(x.x));
        float h1 = __bfloat162float(__float2bfloat16_rn(x.y));
        float h2 = __bfloat162float(__float2bfloat16_rn(x.z));
        float h3 = __bfloat162float(__float2bfloat16_rn(x.w));
        uint2 hi2 = make_uint2(pack_bf16(x.x, x.y), pack_bf16(x.z, x.w));
        uint2 lo2 = make_uint2(pack_bf16(x.x - h0, x.y - h1), pack_bf16(x.z - h2, x.w - h3));
        uint32_t boff = (uint32_t)(r * A_LDE + kq) * 2;
        *(uint2*)(smem + OFF_AHI + boff) = hi2;
        *(uint2*)(smem + OFF_ALO + boff) = lo2;
    }

    // ldmatrix base addresses (canonical row-major A-frag), 2 M-tiles x {hi,lo}
    const uint32_t roff0 = (uint32_t)((wm * 32 + 0  + (lane & 15)) * A_LDE + (lane >> 4) * 8) * 2;
    const uint32_t roff1 = (uint32_t)((wm * 32 + 16 + (lane & 15)) * A_LDE + (lane >> 4) * 8) * 2;
    const uint32_t ah0a = sb + OFF_AHI + roff0;
    const uint32_t ah1a = sb + OFF_AHI + roff1;
    const uint32_t al0a = sb + OFF_ALO + roff0;
    const uint32_t al1a = sb + OFF_ALO + roff1;

    float acc[8][2][4];                                  // [j = gate*2+ct][mtile][creg]
#pragma unroll
    for (int j = 0; j < 8; ++j)
#pragma unroll
        for (int t = 0; t < 2; ++t)
#pragma unroll
            for (int q = 0; q < 4; ++q) acc[j][t][q] = 0.0f;

    // ---- fused mainloop over 8 ksteps ----
#pragma unroll 1
    for (int ks = 0; ks < 8; ++ks) {
        asm volatile("cp.async.wait_group 0;");
        __syncthreads();                                  // B[ks] ready; all warps done with buf[(ks+1)&1]

        if (ks < 7) {                                     // prefetch next kstep
            const char* srch = (const char*)(g_Bhi + ((size_t)head * 8 + ks + 1) * 4096);
            const char* srcl = (const char*)(g_Blo + ((size_t)head * 8 + ks + 1) * 4096);
            uint32_t dst = sb + OFF_B + ((ks + 1) & 1) * B_BUF;
#pragma unroll
            for (int it = 0; it < 2; ++it) {
                int ch = (tid + it * NT) * 16;
                cp16s(dst + ch, srch + ch);
                cp16s(dst + B_SLICE + ch, srcl + ch);
            }
            asm volatile("cp.async.commit_group;");
        }

        uint32_t ah0[4], ah1[4], al0[4], al1[4];
        ldsm4(ah0, ah0a + ks * 32);
        ldsm4(ah1, ah1a + ks * 32);
        ldsm4(al0, al0a + ks * 32);
        ldsm4(al1, al1a + ks * 32);

        const uint32_t bb = sb + OFF_B + (ks & 1) * B_BUF;
#pragma unroll
        for (int j = 0; j < 8; ++j) {
            const int fnt = (j >> 1) * 16 + wn * 2 + (j & 1);
            const uint32_t ba = bb + (uint32_t)(fnt * 32 + lane) * 8;
            uint2 bh = lds64(ba);
            uint2 bl = lds64(ba + B_SLICE);
            mma_bf16(acc[j][0], ah0, bh.x, bh.y);
            mma_bf16(acc[j][1], ah1, bh.x, bh.y);
            mma_bf16(acc[j][0], al0, bh.x, bh.y);
            mma_bf16(acc[j][1], al1, bh.x, bh.y);
            mma_bf16(acc[j][0], ah0, bl.x, bl.y);
            mma_bf16(acc[j][1], ah1, bl.x, bl.y);
        }
    }

    // ---- fused epilogue ----
    const bool allz = (g_any_nonzero == 0);
    const size_t BD = (size_t)Bn * Dn;
    float* out_c = out;
    float* out_n = out + BD;
    float* out_m = out + 2 * BD;
    float* out_h = out + 3 * BD;

#pragma unroll
    for (int mt = 0; mt < 2; ++mt) {
        const int r0 = row0 + wm * 32 + mt * 16 + (lane >> 2);
#pragma unroll
        for (int ct = 0; ct < 2; ++ct) {
            const int col = head * HDn + (wn * 2 + ct) * 8 + (lane & 3) * 2;
            const float2 B_i = *(const float2*)&bi[col];
            const float2 B_f = *(const float2*)&bf[col];
            const float2 B_z = *(const float2*)&bz[col];
            const float2 B_o = *(const float2*)&bo[col];
#pragma unroll
            for (int rr = 0; rr < 2; ++rr) {
                const int row = r0 + rr * 8;
                const size_t idx = (size_t)row * Dn + col;
                const int q0 = rr * 2;                    // c-frag rows m / m+8
                float2 vi = *(const float2*)&gi[idx];
                float2 vf = *(const float2*)&gf[idx];
                float2 vz = *(const float2*)&gz[idx];
                float2 vo = *(const float2*)&go[idx];
                float2 vc = *(const float2*)&gc[idx];
                float2 vn = *(const float2*)&gn[idx];
                float2 vm = *(const float2*)&gm[idx];

                float2 rc, rn_, rm_, rh;
                cell_compute(vi.x + acc[0 + ct][mt][q0]     + B_i.x,
                             vf.x + acc[2 + ct][mt][q0]     + B_f.x,
                             vz.x + acc[4 + ct][mt][q0]     + B_z.x,
                             vo.x + acc[6 + ct][mt][q0]     + B_o.x,
                             vc.x, vn.x, vm.x, allz, rc.x, rn_.x, rm_.x, rh.x);
                cell_compute(vi.y + acc[0 + ct][mt][q0 + 1] + B_i.y,
                             vf.y + acc[2 + ct][mt][q0 + 1] + B_f.y,
                             vz.y + acc[4 + ct][mt][q0 + 1] + B_z.y,
                             vo.y + acc[6 + ct][mt][q0 + 1] + B_o.y,
                             vc.y, vn.y, vm.y, allz, rc.y, rn_.y, rm_.y, rh.y);

                *(float2*)&out_c[idx] = rc;
                *(float2*)&out_n[idx] = rn_;
                *(float2*)&out_m[idx] = rm_;
                *(float2*)&out_h[idx] = rh;
            }
        }
    }
}

// ---------------------------------------------------------------------------
// Launch
// ---------------------------------------------------------------------------
extern "C" void kernel_launch(void* const* d_in, const int* in_sizes, int n_in,
                              void* d_out, int out_size) {
    // metadata order (dict insertion): i, f, z, o, c, m, h, n, Wi, Wf, Wz, Wo, bi, bf, bz, bo
    const float* gi = (const float*)d_in[0];
    const float* gf = (const float*)d_in[1];
    const float* gz = (const float*)d_in[2];
    const float* go = (const float*)d_in[3];
    const float* gc = (const float*)d_in[4];
    const float* gm = (const float*)d_in[5];
    const float* gh = (const float*)d_in[6];
    const float* gn = (const float*)d_in[7];
    const float* Wi = (const float*)d_in[8];
    const float* Wf = (const float*)d_in[9];
    const float* Wz = (const float*)d_in[10];
    const float* Wo = (const float*)d_in[11];
    const float* bi = (const float*)d_in[12];
    const float* bf = (const float*)d_in[13];
    const float* bz = (const float*)d_in[14];
    const float* bo = (const float*)d_in[15];
    float* out = (float*)d_out;

    cudaFuncSetAttribute(slstm_mma_kernel, cudaFuncAttributeMaxDynamicSharedMemorySize,
                         SMEM_BYTES);

    reset_flag_kernel<<<1, 1>>>();
    scan_n_kernel<<<2048, 256>>>((const float4*)gn, (Bn * Dn) / 4);
    convert_w_frag<<<1024, 256>>>(Wi, Wf, Wz, Wo);

    dim3 grid(Bn / BM, Hn);
    slstm_mma_kernel<<<grid, NT, SMEM_BYTES>>>(gi, gf, gz, go, gc, gn, gm, gh,
                                               bi, bf, bz, bo, out);
}